// round 16
// baseline (speedup 1.0000x reference)
#include <cuda_runtime.h>
#include <cuda_fp16.h>
#include <cstdint>
#include <math.h>

#define NC      64
#define DHEAD   128
#define BATCHB  512
#define COLS    8192
#define NPAIRS  2016
#define KC      64              // k-halfs per chunk (128B row)
#define NCH     8
#define PADH    72              // halfs per smem row (stride 144B, conflict-free)
#define ROWB    144
#define A_ST    (DHEAD * ROWB)  // 18432
#define STG     (2 * A_ST)      // 36864 per stage (A+B)
#define NSTG    3
#define SMEM_DYN (NSTG * STG)   // 110592 -> 2 CTAs/SM

// fp16 of 256*q^2, transposed [gram][col][b]  (16.8 MB, L2-resident)
__device__ __half g_Xt[2ULL * COLS * BATCHB];
__device__ float  g_acc[4];     // [0]=dot, [1]=gram a, [2]=gram b, [3]=done counter

__device__ __forceinline__ float fsqrt_fast(float x) {
    float r; asm("sqrt.approx.f32 %0, %1;" : "=f"(r) : "f"(x)); return r;
}
__device__ __forceinline__ uint32_t smem_u32(const void* p) {
    uint32_t a;
    asm("{ .reg .u64 t; cvta.to.shared.u64 t, %1; cvt.u32.u64 %0, t; }" : "=r"(a) : "l"(p));
    return a;
}
#define CP16(dst, src) \
    asm volatile("cp.async.cg.shared.global [%0], [%1], 16;" :: "r"(dst), "l"(src))
#define CP_COMMIT() asm volatile("cp.async.commit_group;" ::: "memory")
#define CP_WAIT1()  asm volatile("cp.async.wait_group 1;"  ::: "memory")
#define CP_WAIT0()  asm volatile("cp.async.wait_group 0;"  ::: "memory")

// ---------------- kernel 0 ----------------
__global__ void k_zero() { if (threadIdx.x < 4) g_acc[threadIdx.x] = 0.0f; }

// ---------------- kernel 1: softmax -> fp16 256*q^2 transposed + self-sim dot ----------------
__global__ void k_softmax(const float* __restrict__ emb) {
    const int c    = blockIdx.y;
    const int b0   = blockIdx.x * 16;
    const int w    = threadIdx.x >> 5;
    const int lane = threadIdx.x & 31;

    __shared__ __align__(16) __half sm_t[2][DHEAD][16];
    __shared__ float dotred[16];

    const int b = b0 + w;
    const float* pa = emb + (size_t)b * COLS + c * DHEAD;
    const float* pb = emb + (size_t)(b + BATCHB) * COLS + c * DHEAD;

    float xa[4], xb[4];
#pragma unroll
    for (int p = 0; p < 4; ++p) { xa[p] = pa[lane + 32 * p]; xb[p] = pb[lane + 32 * p]; }

    float ma = fmaxf(fmaxf(xa[0], xa[1]), fmaxf(xa[2], xa[3]));
    float mb = fmaxf(fmaxf(xb[0], xb[1]), fmaxf(xb[2], xb[3]));
#pragma unroll
    for (int off = 16; off > 0; off >>= 1) {
        ma = fmaxf(ma, __shfl_xor_sync(0xFFFFFFFFu, ma, off));
        mb = fmaxf(mb, __shfl_xor_sync(0xFFFFFFFFu, mb, off));
    }
    float ea[4], eb[4], sa = 0.f, sb = 0.f;
#pragma unroll
    for (int p = 0; p < 4; ++p) {
        ea[p] = __expf(xa[p] - ma); sa += ea[p];
        eb[p] = __expf(xb[p] - mb); sb += eb[p];
    }
#pragma unroll
    for (int off = 16; off > 0; off >>= 1) {
        sa += __shfl_xor_sync(0xFFFFFFFFu, sa, off);
        sb += __shfl_xor_sync(0xFFFFFFFFu, sb, off);
    }
    const float ia = 16.0f / sa, ib = 16.0f / sb;
    float dot = 0.f;
#pragma unroll
    for (int p = 0; p < 4; ++p) {
        float qa = ea[p] * ia;                       // 16*q_a
        float qb = eb[p] * ib;
        dot += qa * qb;                              // 256*qa*qb
        sm_t[0][lane + 32 * p][w] = __float2half_rn(qa * qa);   // 256*q^2
        sm_t[1][lane + 32 * p][w] = __float2half_rn(qb * qb);
    }
#pragma unroll
    for (int off = 16; off > 0; off >>= 1)
        dot += __shfl_xor_sync(0xFFFFFFFFu, dot, off);
    if (lane == 0) dotred[w] = dot;
    __syncthreads();
    if (threadIdx.x == 0) {
        float s = 0.f;
#pragma unroll
        for (int k = 0; k < 16; ++k) s += dotred[k];
        atomicAdd(&g_acc[0], s * (1.0f / 256.0f));
    }
    const int tid = threadIdx.x;
    const int g = tid >> 8;
    const int d = (tid >> 1) & 127;
    const int h = tid & 1;
    uint4 v = *(const uint4*)&sm_t[g][d][h * 8];
    __half* dst = g_Xt + (size_t)g * COLS * BATCHB
                + (size_t)(c * DHEAD + d) * BATCHB + (b0 + h * 8);
    *(uint4*)dst = v;
}

// ---------------- kernel 2: 128x128 Gram tile, HMMA + scalar-LDS frags (R9 core) ----------
// 8 warps 4(row)x2(col), warp tile 32x64, mma m16n8k16 f16->f32, K=512 in 8 chunks.
__global__ void __launch_bounds__(256, 2) k_gram(int gram, float* __restrict__ out) {
    extern __shared__ __align__(16) char dsm[];
    __shared__ float wsum[8];

    const uint32_t sbase = smem_u32(dsm);
    const int tid  = threadIdx.x;
    const int wid  = tid >> 5;
    const int lane = tid & 31;

    // pair decode: t = j*(j-1)/2 + i, i < j
    const int t = blockIdx.x;
    int j = (int)((1.0f + sqrtf(8.0f * (float)t + 1.0f)) * 0.5f);
    while (j * (j - 1) / 2 > t) --j;
    while ((j + 1) * j / 2 <= t) ++j;
    const int i = t - j * (j - 1) / 2;

    const __half* xg = g_Xt + (size_t)gram * COLS * BATCHB;
    const __half* gA = xg + (size_t)j * DHEAD * BATCHB;
    const __half* gB = xg + (size_t)i * DHEAD * BATCHB;

    const int wr = (wid & 3) * 32;
    const int wc = (wid >> 2) * 64;
    const int g4 = lane >> 2;
    const int tg = lane & 3;

    float acc[2][8][4];
#pragma unroll
    for (int a = 0; a < 2; ++a)
#pragma unroll
        for (int b = 0; b < 8; ++b)
#pragma unroll
            for (int c2 = 0; c2 < 4; ++c2) acc[a][b][c2] = 0.f;

    auto load_chunk = [&](int st, int ch) {
        const uint32_t aoff = sbase + st * STG;
        const uint32_t boff = aoff + A_ST;
#pragma unroll
        for (int it = 0; it < 4; ++it) {
            const int u = tid + it * 256;           // 0..1023
            const int r = u >> 3, seg = u & 7;
            const size_t goff = (size_t)r * BATCHB + ch * KC + seg * 8;
            CP16(aoff + r * ROWB + seg * 16, gA + goff);
            CP16(boff + r * ROWB + seg * 16, gB + goff);
        }
        CP_COMMIT();
    };

    load_chunk(0, 0);
    load_chunk(1, 1);

#pragma unroll 1
    for (int ch = 0; ch < NCH; ++ch) {
        if (ch + 1 < NCH) CP_WAIT1(); else CP_WAIT0();
        __syncthreads();
        // issue prefetch of chunk ch+2 BEFORE compute (stage (ch+2)%3 untouched by ch, ch+1)
        if (ch + 2 < NCH) load_chunk((ch + 2) % NSTG, ch + 2);

        const char* pA = dsm + (ch % NSTG) * STG;
        const char* pB = pA + A_ST;

#pragma unroll
        for (int ks = 0; ks < 4; ++ks) {
            const int k0 = ks * 16;
            uint32_t afr[2][4];
#pragma unroll
            for (int rm = 0; rm < 2; ++rm) {
                const int rb = wr + rm * 16;
                afr[rm][0] = *(const uint32_t*)(pA + (rb + g4     ) * ROWB + (k0 + tg * 2    ) * 2);
                afr[rm][1] = *(const uint32_t*)(pA + (rb + g4 + 8 ) * ROWB + (k0 + tg * 2    ) * 2);
                afr[rm][2] = *(const uint32_t*)(pA + (rb + g4     ) * ROWB + (k0 + tg * 2 + 8) * 2);
                afr[rm][3] = *(const uint32_t*)(pA + (rb + g4 + 8 ) * ROWB + (k0 + tg * 2 + 8) * 2);
            }
#pragma unroll
            for (int cn = 0; cn < 8; ++cn) {
                const int nb = wc + cn * 8;
                const uint32_t b0 = *(const uint32_t*)(pB + (nb + g4) * ROWB + (k0 + tg * 2    ) * 2);
                const uint32_t b1 = *(const uint32_t*)(pB + (nb + g4) * ROWB + (k0 + tg * 2 + 8) * 2);
#pragma unroll
                for (int rm = 0; rm < 2; ++rm) {
                    asm volatile(
                        "mma.sync.aligned.m16n8k16.row.col.f32.f16.f16.f32 "
                        "{%0,%1,%2,%3}, {%4,%5,%6,%7}, {%8,%9}, {%0,%1,%2,%3};"
                        : "+f"(acc[rm][cn][0]), "+f"(acc[rm][cn][1]),
                          "+f"(acc[rm][cn][2]), "+f"(acc[rm][cn][3])
                        : "r"(afr[rm][0]), "r"(afr[rm][1]), "r"(afr[rm][2]), "r"(afr[rm][3]),
                          "r"(b0), "r"(b1));
                }
            }
        }
    }

    // epilogue: sum sqrt over all accumulator entries
    float lsum = 0.f;
#pragma unroll
    for (int a = 0; a < 2; ++a)
#pragma unroll
        for (int b = 0; b < 8; ++b)
#pragma unroll
            for (int c2 = 0; c2 < 4; ++c2) lsum += fsqrt_fast(acc[a][b][c2]);
#pragma unroll
    for (int off = 16; off > 0; off >>= 1)
        lsum += __shfl_xor_sync(0xFFFFFFFFu, lsum, off);
    if (lane == 0) wsum[wid] = lsum;
    __syncthreads();
    if (tid == 0) {
        float s = 0.f;
#pragma unroll
        for (int k = 0; k < 8; ++k) s += wsum[k];
        atomicAdd(&g_acc[1 + gram], s);
        __threadfence();
        // completion counter across BOTH k_gram launches (2*NPAIRS CTAs total)
        const unsigned done = (unsigned)atomicAdd(&g_acc[3], 1.0f);
        if (done == 2u * NPAIRS - 1u) {
            // all tiles finished -> finalize
            const float scale = (float)(NC * NC - NC) * sqrtf((float)BATCHB);
            const float self = -g_acc[0] / (float)(BATCHB * NC);
            const float clus = -(2.0f * (g_acc[1] + g_acc[2]) / 256.0f) / (2.0f * scale);
            out[0] = self + clus;
        }
    }
}

extern "C" void kernel_launch(void* const* d_in, const int* in_sizes, int n_in,
                              void* d_out, int out_size) {
    const float* emb = (const float*)d_in[0];
    float* out = (float*)d_out;
    cudaFuncSetAttribute(k_gram, cudaFuncAttributeMaxDynamicSharedMemorySize, SMEM_DYN);
    k_zero<<<1, 32>>>();
    k_softmax<<<dim3(32, 64), 512>>>(emb);
    k_gram<<<NPAIRS, 256, SMEM_DYN>>>(0, out);
    k_gram<<<NPAIRS, 256, SMEM_DYN>>>(1, out);
}

// round 17
// speedup vs baseline: 1.0874x; 1.0874x over previous
#include <cuda_runtime.h>
#include <cuda_fp16.h>
#include <cstdint>
#include <math.h>

#define NC      64
#define DHEAD   128
#define BATCHB  512
#define COLS    8192
#define NPAIRS  2016
#define KC      64              // k-halfs per chunk (128B row)
#define NCH     8
#define ROWB    144             // smem row stride bytes (64 halfs + 8 pad)
#define A_ST    (DHEAD * ROWB)  // 18432
#define STG     (2 * A_ST)      // 36864 per stage (A+B)
#define NSTG    3
#define SMEM_DYN (NSTG * STG)   // 110592 -> 2 CTAs/SM

// fp16 of 256*q^2, transposed [gram][col][b]  (16.8 MB, L2-resident)
__device__ __half g_Xt[2ULL * COLS * BATCHB];
__device__ float  g_acc[4];     // [0]=dot, [1]=gram a, [2]=gram b, [3]=done counter

__device__ __forceinline__ float fsqrt_fast(float x) {
    float r; asm("sqrt.approx.f32 %0, %1;" : "=f"(r) : "f"(x)); return r;
}
__device__ __forceinline__ uint32_t smem_u32(const void* p) {
    uint32_t a;
    asm("{ .reg .u64 t; cvta.to.shared.u64 t, %1; cvt.u32.u64 %0, t; }" : "=r"(a) : "l"(p));
    return a;
}
#define CP16(dst, src) \
    asm volatile("cp.async.cg.shared.global [%0], [%1], 16;" :: "r"(dst), "l"(src))
#define CP_COMMIT() asm volatile("cp.async.commit_group;" ::: "memory")
#define CP_WAIT1()  asm volatile("cp.async.wait_group 1;"  ::: "memory")
#define CP_WAIT0()  asm volatile("cp.async.wait_group 0;"  ::: "memory")

// ---------------- kernel 0 ----------------
__global__ void k_zero() { if (threadIdx.x < 4) g_acc[threadIdx.x] = 0.0f; }

// ---------------- kernel 1: softmax -> fp16 256*q^2 transposed + self-sim dot ----------------
__global__ void k_softmax(const float* __restrict__ emb) {
    const int c    = blockIdx.y;
    const int b0   = blockIdx.x * 16;
    const int w    = threadIdx.x >> 5;
    const int lane = threadIdx.x & 31;

    __shared__ __align__(16) __half sm_t[2][DHEAD][16];
    __shared__ float dotred[16];

    const int b = b0 + w;
    const float* pa = emb + (size_t)b * COLS + c * DHEAD;
    const float* pb = emb + (size_t)(b + BATCHB) * COLS + c * DHEAD;

    float xa[4], xb[4];
#pragma unroll
    for (int p = 0; p < 4; ++p) { xa[p] = pa[lane + 32 * p]; xb[p] = pb[lane + 32 * p]; }

    float ma = fmaxf(fmaxf(xa[0], xa[1]), fmaxf(xa[2], xa[3]));
    float mb = fmaxf(fmaxf(xb[0], xb[1]), fmaxf(xb[2], xb[3]));
#pragma unroll
    for (int off = 16; off > 0; off >>= 1) {
        ma = fmaxf(ma, __shfl_xor_sync(0xFFFFFFFFu, ma, off));
        mb = fmaxf(mb, __shfl_xor_sync(0xFFFFFFFFu, mb, off));
    }
    float ea[4], eb[4], sa = 0.f, sb = 0.f;
#pragma unroll
    for (int p = 0; p < 4; ++p) {
        ea[p] = __expf(xa[p] - ma); sa += ea[p];
        eb[p] = __expf(xb[p] - mb); sb += eb[p];
    }
#pragma unroll
    for (int off = 16; off > 0; off >>= 1) {
        sa += __shfl_xor_sync(0xFFFFFFFFu, sa, off);
        sb += __shfl_xor_sync(0xFFFFFFFFu, sb, off);
    }
    const float ia = 16.0f / sa, ib = 16.0f / sb;
    float dot = 0.f;
#pragma unroll
    for (int p = 0; p < 4; ++p) {
        float qa = ea[p] * ia;                       // 16*q_a
        float qb = eb[p] * ib;
        dot += qa * qb;                              // 256*qa*qb
        sm_t[0][lane + 32 * p][w] = __float2half_rn(qa * qa);   // 256*q^2
        sm_t[1][lane + 32 * p][w] = __float2half_rn(qb * qb);
    }
#pragma unroll
    for (int off = 16; off > 0; off >>= 1)
        dot += __shfl_xor_sync(0xFFFFFFFFu, dot, off);
    if (lane == 0) dotred[w] = dot;
    __syncthreads();
    if (threadIdx.x == 0) {
        float s = 0.f;
#pragma unroll
        for (int k = 0; k < 16; ++k) s += dotred[k];
        atomicAdd(&g_acc[0], s * (1.0f / 256.0f));
    }
    const int tid = threadIdx.x;
    const int g = tid >> 8;
    const int d = (tid >> 1) & 127;
    const int h = tid & 1;
    uint4 v = *(const uint4*)&sm_t[g][d][h * 8];
    __half* dst = g_Xt + (size_t)g * COLS * BATCHB
                + (size_t)(c * DHEAD + d) * BATCHB + (b0 + h * 8);
    *(uint4*)dst = v;
}

// ---------------- kernel 2: 128x128 Gram tile (R9 core) + fused finalize ----------------
// grid (2016, 2): pair x gram. 8 warps 4(row)x2(col), warp tile 32x64,
// mma m16n8k16 f16->f32, K=512 in 8 chunks, 3-stage cp.async, prefetch AFTER compute.
__global__ void __launch_bounds__(256, 2) k_gram(float* __restrict__ out) {
    extern __shared__ __align__(16) char dsm[];
    __shared__ float wsum[8];

    const uint32_t sbase = smem_u32(dsm);
    const int tid  = threadIdx.x;
    const int wid  = tid >> 5;
    const int lane = tid & 31;

    // pair decode: t = j*(j-1)/2 + i, i < j
    const int t = blockIdx.x;
    int j = (int)((1.0f + sqrtf(8.0f * (float)t + 1.0f)) * 0.5f);
    while (j * (j - 1) / 2 > t) --j;
    while ((j + 1) * j / 2 <= t) ++j;
    const int i = t - j * (j - 1) / 2;
    const int gram = blockIdx.y;

    const __half* xg = g_Xt + (size_t)gram * COLS * BATCHB;
    const __half* gA = xg + (size_t)j * DHEAD * BATCHB;
    const __half* gB = xg + (size_t)i * DHEAD * BATCHB;

    const int wr = (wid & 3) * 32;
    const int wc = (wid >> 2) * 64;
    const int g4 = lane >> 2;
    const int tg = lane & 3;

    float acc[2][8][4];
#pragma unroll
    for (int a = 0; a < 2; ++a)
#pragma unroll
        for (int b = 0; b < 8; ++b)
#pragma unroll
            for (int c2 = 0; c2 < 4; ++c2) acc[a][b][c2] = 0.f;

    auto load_chunk = [&](int st, int ch) {
        const uint32_t aoff = sbase + st * STG;
        const uint32_t boff = aoff + A_ST;
#pragma unroll
        for (int it = 0; it < 4; ++it) {
            const int u = tid + it * 256;           // 0..1023
            const int r = u >> 3, seg = u & 7;
            const size_t goff = (size_t)r * BATCHB + ch * KC + seg * 8;
            CP16(aoff + r * ROWB + seg * 16, gA + goff);
            CP16(boff + r * ROWB + seg * 16, gB + goff);
        }
        CP_COMMIT();
    };

    load_chunk(0, 0);
    load_chunk(1, 1);

#pragma unroll 1
    for (int ch = 0; ch < NCH; ++ch) {
        if (ch + 1 < NCH) CP_WAIT1(); else CP_WAIT0();
        __syncthreads();

        const char* pA = dsm + (ch % NSTG) * STG;
        const char* pB = pA + A_ST;

#pragma unroll
        for (int ks = 0; ks < 4; ++ks) {
            const int k0 = ks * 16;
            uint32_t afr[2][4];
#pragma unroll
            for (int rm = 0; rm < 2; ++rm) {
                const int rb = wr + rm * 16;
                afr[rm][0] = *(const uint32_t*)(pA + (rb + g4     ) * ROWB + (k0 + tg * 2    ) * 2);
                afr[rm][1] = *(const uint32_t*)(pA + (rb + g4 + 8 ) * ROWB + (k0 + tg * 2    ) * 2);
                afr[rm][2] = *(const uint32_t*)(pA + (rb + g4     ) * ROWB + (k0 + tg * 2 + 8) * 2);
                afr[rm][3] = *(const uint32_t*)(pA + (rb + g4 + 8 ) * ROWB + (k0 + tg * 2 + 8) * 2);
            }
#pragma unroll
            for (int cn = 0; cn < 8; ++cn) {
                const int nb = wc + cn * 8;
                const uint32_t b0 = *(const uint32_t*)(pB + (nb + g4) * ROWB + (k0 + tg * 2    ) * 2);
                const uint32_t b1 = *(const uint32_t*)(pB + (nb + g4) * ROWB + (k0 + tg * 2 + 8) * 2);
#pragma unroll
                for (int rm = 0; rm < 2; ++rm) {
                    asm volatile(
                        "mma.sync.aligned.m16n8k16.row.col.f32.f16.f16.f32 "
                        "{%0,%1,%2,%3}, {%4,%5,%6,%7}, {%8,%9}, {%0,%1,%2,%3};"
                        : "+f"(acc[rm][cn][0]), "+f"(acc[rm][cn][1]),
                          "+f"(acc[rm][cn][2]), "+f"(acc[rm][cn][3])
                        : "r"(afr[rm][0]), "r"(afr[rm][1]), "r"(afr[rm][2]), "r"(afr[rm][3]),
                          "r"(b0), "r"(b1));
                }
            }
        }
        // prefetch AFTER compute (R9 placement): stage (ch+2)%3 untouched by ch, ch+1
        if (ch + 2 < NCH) load_chunk((ch + 2) % NSTG, ch + 2);
    }

    // epilogue: sum sqrt over all accumulator entries
    float lsum = 0.f;
#pragma unroll
    for (int a = 0; a < 2; ++a)
#pragma unroll
        for (int b = 0; b < 8; ++b)
#pragma unroll
            for (int c2 = 0; c2 < 4; ++c2) lsum += fsqrt_fast(acc[a][b][c2]);
#pragma unroll
    for (int off = 16; off > 0; off >>= 1)
        lsum += __shfl_xor_sync(0xFFFFFFFFu, lsum, off);
    if (lane == 0) wsum[wid] = lsum;
    __syncthreads();
    if (tid == 0) {
        float s = 0.f;
#pragma unroll
        for (int k = 0; k < 8; ++k) s += wsum[k];
        atomicAdd(&g_acc[1 + gram], s);
        __threadfence();
        const unsigned done = (unsigned)atomicAdd(&g_acc[3], 1.0f);
        if (done == 2u * NPAIRS - 1u) {
            // last CTA finalizes: operands 256*q^2 -> sqrt x256; raw_g (i!=j) = 2*acc/256
            const float scale = (float)(NC * NC - NC) * sqrtf((float)BATCHB);
            const float self = -g_acc[0] / (float)(BATCHB * NC);
            const float clus = -(2.0f * (g_acc[1] + g_acc[2]) / 256.0f) / (2.0f * scale);
            out[0] = self + clus;
        }
    }
}

extern "C" void kernel_launch(void* const* d_in, const int* in_sizes, int n_in,
                              void* d_out, int out_size) {
    const float* emb = (const float*)d_in[0];
    float* out = (float*)d_out;
    cudaFuncSetAttribute(k_gram, cudaFuncAttributeMaxDynamicSharedMemorySize, SMEM_DYN);
    k_zero<<<1, 32>>>();
    k_softmax<<<dim3(32, 64), 512>>>(emb);
    k_gram<<<dim3(NPAIRS, 2), 256, SMEM_DYN>>>(out);
}